// round 1
// baseline (speedup 1.0000x reference)
#include <cuda_runtime.h>
#include <cstdint>
#include <cstddef>

// Problem dims
#define D1 64
#define D2 64
#define BB 32
#define II 64
#define OO 128
#define M_TOT (D1 * D2 * BB)   // 131072
#define NPRE  640              // 5 gates * 128

// Scratch: pre-activations [m=(d1,d2,b)][g*128+o], bias folded in.
__device__ float g_pre[(size_t)M_TOT * NPRE];

// ---------------- f32x2 helpers ----------------
__device__ __forceinline__ unsigned long long pack2(float lo, float hi) {
    unsigned long long r;
    asm("mov.b64 %0, {%1, %2};" : "=l"(r) : "f"(lo), "f"(hi));
    return r;
}
__device__ __forceinline__ void unpack2(unsigned long long v, float& lo, float& hi) {
    asm("mov.b64 {%0, %1}, %2;" : "=f"(lo), "=f"(hi) : "l"(v));
}
__device__ __forceinline__ unsigned long long fma2(unsigned long long a,
                                                   unsigned long long b,
                                                   unsigned long long c) {
    unsigned long long d;
    asm("fma.rn.f32x2 %0, %1, %2, %3;" : "=l"(d) : "l"(a), "l"(b), "l"(c));
    return d;
}

// ---------------- math helpers ----------------
__device__ __forceinline__ float sigf(float x) {
    // accurate sigmoid: EX2-based exp + approx reciprocal (~1e-7 rel err)
    return __fdividef(1.0f, 1.0f + __expf(-x));
}
__device__ __forceinline__ float tanhapx(float x) {
    float y;
    asm("tanh.approx.f32 %0, %1;" : "=f"(y) : "f"(x));
    return y;
}

// ================= Kernel 1: projection GEMM =================
// pre[m][g*128+n] = bias_g[n] + sum_k X[m][k] * W_g[k][n]
// grid: (1024 m-tiles, 5 gates), block 256, tile 128m x 128n, K=64 (whole).
__global__ void __launch_bounds__(256, 2) gemm_pre_kernel(
    const float* __restrict__ X,
    const float* __restrict__ wf, const float* __restrict__ wi,
    const float* __restrict__ wo, const float* __restrict__ wc,
    const float* __restrict__ biasf, const float* __restrict__ biasi,
    const float* __restrict__ biaso, const float* __restrict__ biasc)
{
    extern __shared__ float sm[];
    float* Xs = sm;              // [128][64]  (m-major, natural)
    float* Ws = sm + 128 * 64;   // [64][128]  (k-major, natural)

    const int tid = threadIdx.x;
    const int g   = blockIdx.y;
    const int mb  = blockIdx.x * 128;

    const float* W;
    const float* bias;
    if (g == 0)      { W = wf;            bias = biasf;       }
    else if (g == 1) { W = wf + II * OO;  bias = biasf + OO;  }
    else if (g == 2) { W = wi;            bias = biasi;       }
    else if (g == 3) { W = wo;            bias = biaso;       }
    else             { W = wc;            bias = biasc;       }

    // load X tile: 128 rows x 64 floats = 2048 float4
    {
        const float4* X4 = (const float4*)(X + (size_t)mb * II);
        float4* Xs4 = (float4*)Xs;
#pragma unroll
        for (int it = 0; it < 8; it++) {
            int idx = it * 256 + tid;
            Xs4[idx] = X4[idx];
        }
    }
    // load W tile: 64 x 128 = 2048 float4
    {
        const float4* W4 = (const float4*)W;
        float4* Ws4 = (float4*)Ws;
#pragma unroll
        for (int it = 0; it < 8; it++) {
            int idx = it * 256 + tid;
            Ws4[idx] = W4[idx];
        }
    }
    __syncthreads();

    const int tm = tid >> 4;  // 0..15 -> 8 m rows each
    const int tn = tid & 15;  // 0..15 -> 8 n cols each

    unsigned long long acc[8][4];
#pragma unroll
    for (int i = 0; i < 8; i++)
#pragma unroll
        for (int p = 0; p < 4; p++) acc[i][p] = 0ull;

    const float* arow = Xs + tm * 8 * 64;          // 8 consecutive m rows
    const float* bbase = Ws + tn * 8;               // 8 consecutive n cols

#pragma unroll 4
    for (int k = 0; k < 64; k++) {
        // b pairs along n: already adjacent in smem -> read as 64-bit, no packing
        const unsigned long long* bp =
            (const unsigned long long*)(bbase + k * 128);
        unsigned long long b0 = bp[0], b1 = bp[1], b2 = bp[2], b3 = bp[3];
#pragma unroll
        for (int i = 0; i < 8; i++) {
            float a = arow[i * 64 + k];             // broadcast LDS (2 addrs/warp)
            unsigned long long a2 = pack2(a, a);
            acc[i][0] = fma2(a2, b0, acc[i][0]);
            acc[i][1] = fma2(a2, b1, acc[i][1]);
            acc[i][2] = fma2(a2, b2, acc[i][2]);
            acc[i][3] = fma2(a2, b3, acc[i][3]);
        }
    }

    float bs[8];
#pragma unroll
    for (int j = 0; j < 8; j++) bs[j] = bias[tn * 8 + j];

#pragma unroll
    for (int i = 0; i < 8; i++) {
        float c[8];
#pragma unroll
        for (int p = 0; p < 4; p++) unpack2(acc[i][p], c[2 * p], c[2 * p + 1]);
#pragma unroll
        for (int j = 0; j < 8; j++) c[j] += bs[j];
        int m = mb + tm * 8 + i;
        float4* dst = (float4*)(g_pre + (size_t)m * NPRE + g * 128 + tn * 8);
        dst[0] = make_float4(c[0], c[1], c[2], c[3]);
        dst[1] = make_float4(c[4], c[5], c[6], c[7]);
    }
}

// ================= Kernel 2: wavefront recurrence =================
struct UC {
    float uf00, uf01, uf10, uf11;
    float ui0, ui1, uo0, uo1, uc0, uc1;
};

__device__ __forceinline__ void cell_compute(const float q[5], const UC& u,
                                             float hup, float hl,
                                             float sup, float sl,
                                             float& s, float& h)
{
    float pf0 = fmaf(u.uf01, hl, fmaf(u.uf00, hup, q[0]));
    float pf1 = fmaf(u.uf11, hl, fmaf(u.uf10, hup, q[1]));
    float pi  = fmaf(u.ui1,  hl, fmaf(u.ui0,  hup, q[2]));
    float po  = fmaf(u.uo1,  hl, fmaf(u.uo0,  hup, q[3]));
    float pc  = fmaf(u.uc1,  hl, fmaf(u.uc0,  hup, q[4]));
    float f0 = sigf(pf0);
    float f1 = sigf(pf1);
    float ig = sigf(pi);
    float og = sigf(po);
    float cg = sigf(pc);
    s = fmaf(f0, sup, fmaf(f1, sl, ig * cg));
    h = og * tanhapx(s);
}

// block = (b, o-group of 32). 32 warps; warp w owns rows 2w, 2w+1; lane = o.
// Diagonal stepping with double-buffered smem handoff between warps.
__global__ void __launch_bounds__(1024, 1) mdlstm_rec_kernel(
    const float* __restrict__ uf, const float* __restrict__ ui,
    const float* __restrict__ uo, const float* __restrict__ uc,
    float* __restrict__ out)
{
    __shared__ float sh_s[2][32][32];
    __shared__ float sh_h[2][32][32];

    const int lane = threadIdx.x & 31;
    const int w    = threadIdx.x >> 5;
    const int b    = blockIdx.x >> 2;
    const int og   = blockIdx.x & 3;
    const int o    = og * 32 + lane;

    UC u;
    u.uf00 = uf[o];        u.uf01 = uf[128 + o];
    u.uf10 = uf[256 + o];  u.uf11 = uf[384 + o];
    u.ui0  = ui[o];        u.ui1  = ui[128 + o];
    u.uo0  = uo[o];        u.uo1  = uo[128 + o];
    u.uc0  = uc[o];        u.uc1  = uc[128 + o];

    const float* preb = g_pre + (size_t)b * NPRE + o;  // + cell*20480
    float* ob = out + b * 128 + o;                     // + cell*4096

    const int r0base = (2 * w) * 64;   // row 2w cell-row offset
    const int r1base = r0base + 64;    // row 2w+1

    float s0l = 0.f, h0l = 0.f;  // row0 left-neighbor state
    float s1l = 0.f, h1l = 0.f;  // row1 left-neighbor state

    float q0[5], q1[5];
    // prefetch for t = 0 (only warp 0 row0 is active)
    if (w == 0) {
        const float* p = preb;  // cell (0,0)
        q0[0] = __ldg(p);       q0[1] = __ldg(p + 128);
        q0[2] = __ldg(p + 256); q0[3] = __ldg(p + 384);
        q0[4] = __ldg(p + 512);
    }

    for (int t = 0; t <= 126; t++) {
        const int c0 = t - 2 * w;
        const int c1 = c0 - 1;
        const bool a0 = (c0 >= 0) && (c0 < 64);
        const bool a1 = (c1 >= 0) && (c1 < 64);
        const int cb = t & 1, pbuf = cb ^ 1;

        // ---- prefetch pre-activations for step t+1 (hide DRAM latency) ----
        float n0[5], n1[5];
        {
            const int c0n = c0 + 1, c1n = c1 + 1;
            if (c0n >= 0 && c0n < 64) {
                const float* p = preb + (size_t)(r0base + c0n) * 20480;
                n0[0] = __ldg(p);       n0[1] = __ldg(p + 128);
                n0[2] = __ldg(p + 256); n0[3] = __ldg(p + 384);
                n0[4] = __ldg(p + 512);
            }
            if (c1n >= 0 && c1n < 64) {
                const float* p = preb + (size_t)(r1base + c1n) * 20480;
                n1[0] = __ldg(p);       n1[1] = __ldg(p + 128);
                n1[2] = __ldg(p + 256); n1[3] = __ldg(p + 384);
                n1[4] = __ldg(p + 512);
            }
        }

        // row0's previous-step output = up-neighbor for row1 this step
        const float s0_prev = s0l, h0_prev = h0l;

        if (a0) {
            if (c0 == 0) { s0l = 0.f; h0l = 0.f; }
            float sup, hup;
            if (w == 0) { sup = 0.f; hup = 0.f; }
            else { sup = sh_s[pbuf][w - 1][lane]; hup = sh_h[pbuf][w - 1][lane]; }
            float s, h;
            cell_compute(q0, u, hup, h0l, sup, s0l, s, h);
            ob[(r0base + c0) * 4096] = s;
            s0l = s; h0l = h;
        }
        if (a1) {
            if (c1 == 0) { s1l = 0.f; h1l = 0.f; }
            float s, h;
            cell_compute(q1, u, h0_prev, h1l, s0_prev, s1l, s, h);
            ob[(r1base + c1) * 4096] = s;
            s1l = s; h1l = h;
            // publish odd row for warp w+1 (consumed at step t+1)
            sh_s[cb][w][lane] = s;
            sh_h[cb][w][lane] = h;
        }

        // rotate prefetch registers (garbage when inactive next step — unused)
#pragma unroll
        for (int z = 0; z < 5; z++) { q0[z] = n0[z]; q1[z] = n1[z]; }

        __syncthreads();
    }
}

// ================= launcher =================
extern "C" void kernel_launch(void* const* d_in, const int* in_sizes, int n_in,
                              void* d_out, int out_size) {
    (void)in_sizes; (void)n_in; (void)out_size;
    const float* x     = (const float*)d_in[0];
    const float* wf    = (const float*)d_in[1];
    const float* uf    = (const float*)d_in[2];
    const float* biasf = (const float*)d_in[3];
    const float* wi    = (const float*)d_in[4];
    const float* ui    = (const float*)d_in[5];
    const float* biasi = (const float*)d_in[6];
    const float* wo    = (const float*)d_in[7];
    const float* uo    = (const float*)d_in[8];
    const float* biaso = (const float*)d_in[9];
    const float* wc    = (const float*)d_in[10];
    const float* uc    = (const float*)d_in[11];
    const float* biasc = (const float*)d_in[12];
    float* out = (float*)d_out;

    cudaFuncSetAttribute(gemm_pre_kernel,
                         cudaFuncAttributeMaxDynamicSharedMemorySize, 64 * 1024);
    gemm_pre_kernel<<<dim3(1024, 5), 256, 64 * 1024>>>(
        x, wf, wi, wo, wc, biasf, biasi, biaso, biasc);
    mdlstm_rec_kernel<<<128, 1024>>>(uf, ui, uo, uc, out);
}

// round 3
// speedup vs baseline: 1.3359x; 1.3359x over previous
#include <cuda_runtime.h>
#include <cuda_bf16.h>
#include <cstdint>
#include <cstddef>

// Problem dims
#define D1 64
#define D2 64
#define BB 32
#define II 64
#define OO 128
#define M_TOT (D1 * D2 * BB)   // 131072
#define NPRE  640              // 5 gates * 128

// Scratch: pre-activations [m=(d1,d2,b)][g*128+o], bias folded in.
__device__ float g_pre[(size_t)M_TOT * NPRE];

// ========================= helpers =========================
__device__ __forceinline__ uint32_t smem_u32(const void* p) {
    uint32_t a;
    asm("{ .reg .u64 t; cvta.to.shared.u64 t, %1; cvt.u32.u64 %0, t; }"
        : "=r"(a) : "l"(p));
    return a;
}

__device__ __forceinline__ void ldsm_x4(uint32_t& r0, uint32_t& r1,
                                        uint32_t& r2, uint32_t& r3,
                                        uint32_t addr) {
    asm volatile("ldmatrix.sync.aligned.m8n8.x4.shared.b16 {%0,%1,%2,%3}, [%4];"
                 : "=r"(r0), "=r"(r1), "=r"(r2), "=r"(r3) : "r"(addr));
}

// D += A * B  (m16n8k16, bf16 in, f32 accum)
__device__ __forceinline__ void mma_bf16(float* d, const uint32_t* a,
                                         uint32_t b0, uint32_t b1) {
    asm volatile(
        "mma.sync.aligned.m16n8k16.row.col.f32.bf16.bf16.f32 "
        "{%0,%1,%2,%3}, {%4,%5,%6,%7}, {%8,%9}, {%0,%1,%2,%3};"
        : "+f"(d[0]), "+f"(d[1]), "+f"(d[2]), "+f"(d[3])
        : "r"(a[0]), "r"(a[1]), "r"(a[2]), "r"(a[3]), "r"(b0), "r"(b1));
}

// bf16 hi/lo split of an fp32 value (hi = rn(v), lo = rn(v - hi))
__device__ __forceinline__ void bfsplit(float v, uint32_t& hi, uint32_t& lo) {
    __nv_bfloat16 h = __float2bfloat16(v);
    float r = v - __bfloat162float(h);
    __nv_bfloat16 l = __float2bfloat16(r);
    hi = (uint32_t)(*reinterpret_cast<unsigned short*>(&h));
    lo = (uint32_t)(*reinterpret_cast<unsigned short*>(&l));
}

// ================= Kernel 1: HMMA bf16 3-split projection GEMM =============
// pre[m][g*128+n] = bias_g[n] + sum_k X[m][k] * W_g[k][n]
// grid = 1024 m-tiles of 128; block 256 (8 warps: 4m x 2n); 5 gates looped.
#define A_STR 72   // padded row stride (elements) -> 144 B, conflict-free ldsm
#define B_STR 72

#define SM_AH 0
#define SM_AL 18432
#define SM_BH 36864
#define SM_BL 55296
#define SM_TOTAL 73728

__global__ void __launch_bounds__(256, 2) gemm_pre_hmma(
    const float* __restrict__ X,
    const float* __restrict__ wf, const float* __restrict__ wi,
    const float* __restrict__ wo, const float* __restrict__ wc,
    const float* __restrict__ biasf, const float* __restrict__ biasi,
    const float* __restrict__ biaso, const float* __restrict__ biasc)
{
    extern __shared__ __align__(1024) char sm[];
    const uint32_t sbase = smem_u32(sm);
    const int tid  = threadIdx.x;
    const int lane = tid & 31;
    const int w    = tid >> 5;
    const int wm   = w >> 1;      // 0..3  (m quadrant, 32 rows)
    const int wn   = w & 1;       // 0..1  (n half, 64 cols)
    const int mb   = blockIdx.x * 128;

    // ---- load + split X tile: 128 rows x 64 fp32 -> A_hi / A_lo bf16 ----
    {
        const float4* X4 = (const float4*)(X + (size_t)mb * II);
#pragma unroll
        for (int it = 0; it < 8; it++) {
            int j = tid + it * 256;          // 2048 float4 total
            float4 v = X4[j];
            int row = j >> 4;
            int kq  = (j & 15) * 4;
            uint32_t h0, l0, h1, l1, h2, l2, h3, l3;
            bfsplit(v.x, h0, l0); bfsplit(v.y, h1, l1);
            bfsplit(v.z, h2, l2); bfsplit(v.w, h3, l3);
            uint32_t off = (uint32_t)(row * (A_STR * 2) + kq * 2);
            *(uint2*)(sm + SM_AH + off) = make_uint2(h0 | (h1 << 16), h2 | (h3 << 16));
            *(uint2*)(sm + SM_AL + off) = make_uint2(l0 | (l1 << 16), l2 | (l3 << 16));
        }
    }

    // ldmatrix lane addresses (row = lane&15, col-half = lane>>4)
    const int lrow = lane & 15;
    const int lcolb = (lane >> 4) * 16;     // byte offset of k-half
    // A: row = wm*32 + mi*16 + lrow
    uint32_t aAddrH[2], aAddrL[2];
#pragma unroll
    for (int mi = 0; mi < 2; mi++) {
        uint32_t ro = (uint32_t)((wm * 32 + mi * 16 + lrow) * (A_STR * 2) + lcolb);
        aAddrH[mi] = sbase + SM_AH + ro;
        aAddrL[mi] = sbase + SM_AL + ro;
    }
    // B: row(n) = wn*64 + p*16 + lrow
    uint32_t bAddrH[4], bAddrL[4];
#pragma unroll
    for (int p = 0; p < 4; p++) {
        uint32_t ro = (uint32_t)((wn * 64 + p * 16 + lrow) * (B_STR * 2) + lcolb);
        bAddrH[p] = sbase + SM_BH + ro;
        bAddrL[p] = sbase + SM_BL + ro;
    }

#pragma unroll 1
    for (int g = 0; g < 5; g++) {
        const float* W;
        const float* bias;
        if (g == 0)      { W = wf;            bias = biasf;       }
        else if (g == 1) { W = wf + II * OO;  bias = biasf + OO;  }
        else if (g == 2) { W = wi;            bias = biasi;       }
        else if (g == 3) { W = wo;            bias = biaso;       }
        else             { W = wc;            bias = biasc;       }

        // ---- load + split + transpose W_g -> Bsm[n][k] ----
        {
            const int n    = tid & 127;
            const int half = tid >> 7;       // k half: 0 or 1
#pragma unroll
            for (int i = 0; i < 16; i++) {
                int k0 = half * 32 + 2 * i;
                float w0 = __ldg(W + (size_t)k0 * OO + n);
                float w1 = __ldg(W + (size_t)(k0 + 1) * OO + n);
                uint32_t h0, l0, h1, l1;
                bfsplit(w0, h0, l0); bfsplit(w1, h1, l1);
                uint32_t off = (uint32_t)(n * (B_STR * 2) + k0 * 2);
                *(uint32_t*)(sm + SM_BH + off) = h0 | (h1 << 16);
                *(uint32_t*)(sm + SM_BL + off) = l0 | (l1 << 16);
            }
        }
        __syncthreads();

        // ---- main MMA: 4 k-steps x (2m x 8n) x 3 split terms ----
        float acc[2][8][4];
#pragma unroll
        for (int mi = 0; mi < 2; mi++)
#pragma unroll
            for (int ni = 0; ni < 8; ni++)
#pragma unroll
                for (int e = 0; e < 4; e++) acc[mi][ni][e] = 0.f;

#pragma unroll
        for (int ks = 0; ks < 4; ks++) {
            const uint32_t kb = (uint32_t)(ks * 32);   // 16 elems = 32 B
            uint32_t aH[2][4], aL[2][4];
#pragma unroll
            for (int mi = 0; mi < 2; mi++) {
                ldsm_x4(aH[mi][0], aH[mi][1], aH[mi][2], aH[mi][3], aAddrH[mi] + kb);
                ldsm_x4(aL[mi][0], aL[mi][1], aL[mi][2], aL[mi][3], aAddrL[mi] + kb);
            }
#pragma unroll
            for (int p = 0; p < 4; p++) {
                uint32_t bh0, bh1, bh2, bh3, bl0, bl1, bl2, bl3;
                ldsm_x4(bh0, bh1, bh2, bh3, bAddrH[p] + kb);
                ldsm_x4(bl0, bl1, bl2, bl3, bAddrL[p] + kb);
#pragma unroll
                for (int mi = 0; mi < 2; mi++) {
                    // hi*hi
                    mma_bf16(acc[mi][2 * p],     aH[mi], bh0, bh2);
                    mma_bf16(acc[mi][2 * p + 1], aH[mi], bh1, bh3);
                    // lo*hi
                    mma_bf16(acc[mi][2 * p],     aL[mi], bh0, bh2);
                    mma_bf16(acc[mi][2 * p + 1], aL[mi], bh1, bh3);
                    // hi*lo
                    mma_bf16(acc[mi][2 * p],     aH[mi], bl0, bl2);
                    mma_bf16(acc[mi][2 * p + 1], aH[mi], bl1, bl3);
                }
            }
        }

        // ---- epilogue: bias + store (STG.64, 32B sectors fully used) ----
        {
            const int qr = lane >> 2;          // 0..7 row within 8
            const int qc = (lane & 3) * 2;     // col pair within 8
#pragma unroll
            for (int ni = 0; ni < 8; ni++) {
                int col = wn * 64 + ni * 8 + qc;
                float b0 = __ldg(bias + col);
                float b1 = __ldg(bias + col + 1);
#pragma unroll
                for (int mi = 0; mi < 2; mi++) {
                    int row = mb + wm * 32 + mi * 16 + qr;
                    size_t idx = (size_t)row * NPRE + (size_t)g * 128 + col;
                    float2 v0 = make_float2(acc[mi][ni][0] + b0, acc[mi][ni][1] + b1);
                    float2 v1 = make_float2(acc[mi][ni][2] + b0, acc[mi][ni][3] + b1);
                    *(float2*)(g_pre + idx) = v0;
                    *(float2*)(g_pre + idx + 8 * NPRE) = v1;
                }
            }
        }
        __syncthreads();   // before overwriting B for next gate
    }
}

// ================= Kernel 2: wavefront recurrence =================
__device__ __forceinline__ float sigf(float x) {
    // sigma(x) = 0.5*tanh(x/2) + 0.5  -- single MUFU
    float t;
    asm("tanh.approx.f32 %0, %1;" : "=f"(t) : "f"(0.5f * x));
    return fmaf(0.5f, t, 0.5f);
}
__device__ __forceinline__ float tanhapx(float x) {
    float y;
    asm("tanh.approx.f32 %0, %1;" : "=f"(y) : "f"(x));
    return y;
}

struct UC {
    float uf00, uf01, uf10, uf11;
    float ui0, ui1, uo0, uo1, uc0, uc1;
};

__device__ __forceinline__ void cell_compute(const float q[5], const UC& u,
                                             float hup, float hl,
                                             float sup, float sl,
                                             float& s, float& h)
{
    float pf0 = fmaf(u.uf01, hl, fmaf(u.uf00, hup, q[0]));
    float pf1 = fmaf(u.uf11, hl, fmaf(u.uf10, hup, q[1]));
    float pi  = fmaf(u.ui1,  hl, fmaf(u.ui0,  hup, q[2]));
    float po  = fmaf(u.uo1,  hl, fmaf(u.uo0,  hup, q[3]));
    float pc  = fmaf(u.uc1,  hl, fmaf(u.uc0,  hup, q[4]));
    float f0 = sigf(pf0);
    float f1 = sigf(pf1);
    float ig = sigf(pi);
    float og = sigf(po);
    float cg = sigf(pc);
    s = fmaf(f0, sup, fmaf(f1, sl, ig * cg));
    h = og * tanhapx(s);
}

// block = (b, o-group of 32). 32 warps; warp w owns rows 2w, 2w+1; lane = o.
__global__ void __launch_bounds__(1024, 1) mdlstm_rec_kernel(
    const float* __restrict__ uf, const float* __restrict__ ui,
    const float* __restrict__ uo, const float* __restrict__ uc,
    float* __restrict__ out)
{
    __shared__ float sh_s[2][32][32];
    __shared__ float sh_h[2][32][32];

    const int lane = threadIdx.x & 31;
    const int w    = threadIdx.x >> 5;
    const int b    = blockIdx.x >> 2;
    const int og   = blockIdx.x & 3;
    const int o    = og * 32 + lane;

    UC u;
    u.uf00 = uf[o];        u.uf01 = uf[128 + o];
    u.uf10 = uf[256 + o];  u.uf11 = uf[384 + o];
    u.ui0  = ui[o];        u.ui1  = ui[128 + o];
    u.uo0  = uo[o];        u.uo1  = uo[128 + o];
    u.uc0  = uc[o];        u.uc1  = uc[128 + o];

    const float* preb = g_pre + (size_t)b * NPRE + o;  // + cell*20480
    float* ob = out + b * 128 + o;                     // + cell*4096

    const int r0base = (2 * w) * 64;
    const int r1base = r0base + 64;

    float s0l = 0.f, h0l = 0.f;
    float s1l = 0.f, h1l = 0.f;

    float q0[5], q1[5];
    if (w == 0) {
        const float* p = preb;
        q0[0] = __ldg(p);       q0[1] = __ldg(p + 128);
        q0[2] = __ldg(p + 256); q0[3] = __ldg(p + 384);
        q0[4] = __ldg(p + 512);
    }

    for (int t = 0; t <= 126; t++) {
        const int c0 = t - 2 * w;
        const int c1 = c0 - 1;
        const bool a0 = (c0 >= 0) && (c0 < 64);
        const bool a1 = (c1 >= 0) && (c1 < 64);
        const int cb = t & 1, pbuf = cb ^ 1;

        float n0[5], n1[5];
        {
            const int c0n = c0 + 1, c1n = c1 + 1;
            if (c0n >= 0 && c0n < 64) {
                const float* p = preb + (size_t)(r0base + c0n) * 20480;
                n0[0] = __ldg(p);       n0[1] = __ldg(p + 128);
                n0[2] = __ldg(p + 256); n0[3] = __ldg(p + 384);
                n0[4] = __ldg(p + 512);
            }
            if (c1n >= 0 && c1n < 64) {
                const float* p = preb + (size_t)(r1base + c1n) * 20480;
                n1[0] = __ldg(p);       n1[1] = __ldg(p + 128);
                n1[2] = __ldg(p + 256); n1[3] = __ldg(p + 384);
                n1[4] = __ldg(p + 512);
            }
        }

        const float s0_prev = s0l, h0_prev = h0l;

        if (a0) {
            if (c0 == 0) { s0l = 0.f; h0l = 0.f; }
            float sup, hup;
            if (w == 0) { sup = 0.f; hup = 0.f; }
            else { sup = sh_s[pbuf][w - 1][lane]; hup = sh_h[pbuf][w - 1][lane]; }
            float s, h;
            cell_compute(q0, u, hup, h0l, sup, s0l, s, h);
            ob[(r0base + c0) * 4096] = s;
            s0l = s; h0l = h;
        }
        if (a1) {
            if (c1 == 0) { s1l = 0.f; h1l = 0.f; }
            float s, h;
            cell_compute(q1, u, h0_prev, h1l, s0_prev, s1l, s, h);
            ob[(r1base + c1) * 4096] = s;
            s1l = s; h1l = h;
            sh_s[cb][w][lane] = s;
            sh_h[cb][w][lane] = h;
        }

#pragma unroll
        for (int z = 0; z < 5; z++) { q0[z] = n0[z]; q1[z] = n1[z]; }

        __syncthreads();
    }
}

// ================= launcher =================
extern "C" void kernel_launch(void* const* d_in, const int* in_sizes, int n_in,
                              void* d_out, int out_size) {
    (void)in_sizes; (void)n_in; (void)out_size;
    const float* x     = (const float*)d_in[0];
    const float* wf    = (const float*)d_in[1];
    const float* uf    = (const float*)d_in[2];
    const float* biasf = (const float*)d_in[3];
    const float* wi    = (const float*)d_in[4];
    const float* ui    = (const float*)d_in[5];
    const float* biasi = (const float*)d_in[6];
    const float* wo    = (const float*)d_in[7];
    const float* uo    = (const float*)d_in[8];
    const float* biaso = (const float*)d_in[9];
    const float* wc    = (const float*)d_in[10];
    const float* uc    = (const float*)d_in[11];
    const float* biasc = (const float*)d_in[12];
    float* out = (float*)d_out;

    cudaFuncSetAttribute(gemm_pre_hmma,
                         cudaFuncAttributeMaxDynamicSharedMemorySize, SM_TOTAL);
    gemm_pre_hmma<<<1024, 256, SM_TOTAL>>>(
        x, wf, wi, wo, wc, biasf, biasi, biaso, biasc);
    mdlstm_rec_kernel<<<128, 1024>>>(uf, ui, uo, uc, out);
}

// round 4
// speedup vs baseline: 1.3376x; 1.0013x over previous
#include <cuda_runtime.h>
#include <cuda_bf16.h>
#include <cstdint>
#include <cstddef>

// Problem dims
#define D1 64
#define D2 64
#define BB 32
#define II 64
#define OO 128
#define M_TOT (D1 * D2 * BB)   // 131072
#define NPRE  640              // 5 gates * 128

// Scratch: pre-activations [m=(d1,d2,b)][g*128+o], bias folded in.
__device__ float g_pre[(size_t)M_TOT * NPRE];

// ========================= helpers =========================
__device__ __forceinline__ uint32_t smem_u32(const void* p) {
    uint32_t a;
    asm("{ .reg .u64 t; cvta.to.shared.u64 t, %1; cvt.u32.u64 %0, t; }"
        : "=r"(a) : "l"(p));
    return a;
}

__device__ __forceinline__ void ldsm_x4(uint32_t& r0, uint32_t& r1,
                                        uint32_t& r2, uint32_t& r3,
                                        uint32_t addr) {
    asm volatile("ldmatrix.sync.aligned.m8n8.x4.shared.b16 {%0,%1,%2,%3}, [%4];"
                 : "=r"(r0), "=r"(r1), "=r"(r2), "=r"(r3) : "r"(addr));
}

// D += A * B  (m16n8k16, bf16 in, f32 accum)
__device__ __forceinline__ void mma_bf16(float* d, const uint32_t* a,
                                         uint32_t b0, uint32_t b1) {
    asm volatile(
        "mma.sync.aligned.m16n8k16.row.col.f32.bf16.bf16.f32 "
        "{%0,%1,%2,%3}, {%4,%5,%6,%7}, {%8,%9}, {%0,%1,%2,%3};"
        : "+f"(d[0]), "+f"(d[1]), "+f"(d[2]), "+f"(d[3])
        : "r"(a[0]), "r"(a[1]), "r"(a[2]), "r"(a[3]), "r"(b0), "r"(b1));
}

// bf16 hi/lo split of an fp32 value (hi = rn(v), lo = rn(v - hi))
__device__ __forceinline__ void bfsplit(float v, uint32_t& hi, uint32_t& lo) {
    __nv_bfloat16 h = __float2bfloat16(v);
    float r = v - __bfloat162float(h);
    __nv_bfloat16 l = __float2bfloat16(r);
    hi = (uint32_t)(*reinterpret_cast<unsigned short*>(&h));
    lo = (uint32_t)(*reinterpret_cast<unsigned short*>(&l));
}

// ================= Kernel 1: HMMA bf16 3-split projection GEMM =============
// pre[m][g*128+n] = bias_g[n] + sum_k X[m][k] * W_g[k][n]
// grid = 1024 m-tiles of 128; block 512 (16 warps: 4m x 4n).
// ALL 5 gates' B tiles resident in smem -> ONE barrier, then pure streaming.
#define A_STR 72   // padded row stride (elements) -> 144 B, conflict-free ldsm
#define B_STR 72

#define SM_AH 0
#define SM_AL 18432
#define SM_B  36864                       // [g][hi/lo] each 18432 B
#define SM_TOTAL (36864 + 5 * 36864)      // 221184

__global__ void __launch_bounds__(512, 1) gemm_pre_hmma(
    const float* __restrict__ X,
    const float* __restrict__ wf, const float* __restrict__ wi,
    const float* __restrict__ wo, const float* __restrict__ wc,
    const float* __restrict__ biasf, const float* __restrict__ biasi,
    const float* __restrict__ biaso, const float* __restrict__ biasc)
{
    extern __shared__ __align__(1024) char sm[];
    const uint32_t sbase = smem_u32(sm);
    const int tid  = threadIdx.x;
    const int lane = tid & 31;
    const int w    = tid >> 5;
    const int wm   = w >> 2;      // 0..3  (m quadrant, 32 rows)
    const int wn   = w & 3;       // 0..3  (n quarter, 32 cols)
    const int mb   = blockIdx.x * 128;

    // ---- load + split X tile: 128 rows x 64 fp32 -> A_hi / A_lo bf16 ----
    {
        const float4* X4 = (const float4*)(X + (size_t)mb * II);
#pragma unroll
        for (int it = 0; it < 4; it++) {
            int j = tid + it * 512;          // 2048 float4 total
            float4 v = X4[j];
            int row = j >> 4;
            int kq  = (j & 15) * 4;
            uint32_t h0, l0, h1, l1, h2, l2, h3, l3;
            bfsplit(v.x, h0, l0); bfsplit(v.y, h1, l1);
            bfsplit(v.z, h2, l2); bfsplit(v.w, h3, l3);
            uint32_t off = (uint32_t)(row * (A_STR * 2) + kq * 2);
            *(uint2*)(sm + SM_AH + off) = make_uint2(h0 | (h1 << 16), h2 | (h3 << 16));
            *(uint2*)(sm + SM_AL + off) = make_uint2(l0 | (l1 << 16), l2 | (l3 << 16));
        }
    }

    // ---- load + split + transpose ALL gate weights -> Bsm[g][n][k] ----
    {
        const int n  = tid & 127;
        const int qu = tid >> 7;             // k quarter: 0..3
#pragma unroll 1
        for (int g = 0; g < 5; g++) {
            const float* W;
            if (g == 0)      W = wf;
            else if (g == 1) W = wf + II * OO;
            else if (g == 2) W = wi;
            else if (g == 3) W = wo;
            else             W = wc;
            char* bh = sm + SM_B + g * 36864;
            char* bl = bh + 18432;
#pragma unroll
            for (int i = 0; i < 8; i++) {
                int k0 = qu * 16 + 2 * i;
                float w0 = __ldg(W + (size_t)k0 * OO + n);
                float w1 = __ldg(W + (size_t)(k0 + 1) * OO + n);
                uint32_t h0, l0, h1, l1;
                bfsplit(w0, h0, l0); bfsplit(w1, h1, l1);
                uint32_t off = (uint32_t)(n * (B_STR * 2) + k0 * 2);
                *(uint32_t*)(bh + off) = h0 | (h1 << 16);
                *(uint32_t*)(bl + off) = l0 | (l1 << 16);
            }
        }
    }
    __syncthreads();   // the ONLY block barrier

    // ldmatrix lane addresses (row = lane&15, col-half = lane>>4)
    const int lrow  = lane & 15;
    const int lcolb = (lane >> 4) * 16;     // byte offset of k-half
    uint32_t aAddrH[2], aAddrL[2];
#pragma unroll
    for (int mi = 0; mi < 2; mi++) {
        uint32_t ro = (uint32_t)((wm * 32 + mi * 16 + lrow) * (A_STR * 2) + lcolb);
        aAddrH[mi] = sbase + SM_AH + ro;
        aAddrL[mi] = sbase + SM_AL + ro;
    }
    // B lane base (per gate add g*36864; hi at +0, lo at +18432)
    uint32_t bAddr[2];
#pragma unroll
    for (int p = 0; p < 2; p++) {
        uint32_t ro = (uint32_t)((wn * 32 + p * 16 + lrow) * (B_STR * 2) + lcolb);
        bAddr[p] = sbase + SM_B + ro;
    }

    // A fragments hoisted: reused across all 5 gates
    uint32_t aH[4][2][4], aL[4][2][4];
#pragma unroll
    for (int ks = 0; ks < 4; ks++) {
        const uint32_t kb = (uint32_t)(ks * 32);
#pragma unroll
        for (int mi = 0; mi < 2; mi++) {
            ldsm_x4(aH[ks][mi][0], aH[ks][mi][1], aH[ks][mi][2], aH[ks][mi][3],
                    aAddrH[mi] + kb);
            ldsm_x4(aL[ks][mi][0], aL[ks][mi][1], aL[ks][mi][2], aL[ks][mi][3],
                    aAddrL[mi] + kb);
        }
    }

#pragma unroll 1
    for (int g = 0; g < 5; g++) {
        const float* bias;
        if (g == 0)      bias = biasf;
        else if (g == 1) bias = biasf + OO;
        else if (g == 2) bias = biasi;
        else if (g == 3) bias = biaso;
        else             bias = biasc;
        const uint32_t goff = (uint32_t)(g * 36864);

        float acc[2][4][4];
#pragma unroll
        for (int mi = 0; mi < 2; mi++)
#pragma unroll
            for (int ni = 0; ni < 4; ni++)
#pragma unroll
                for (int e = 0; e < 4; e++) acc[mi][ni][e] = 0.f;

#pragma unroll
        for (int ks = 0; ks < 4; ks++) {
            const uint32_t kb = (uint32_t)(ks * 32);
#pragma unroll
            for (int p = 0; p < 2; p++) {
                uint32_t bh0, bh1, bh2, bh3, bl0, bl1, bl2, bl3;
                ldsm_x4(bh0, bh1, bh2, bh3, bAddr[p] + goff + kb);
                ldsm_x4(bl0, bl1, bl2, bl3, bAddr[p] + goff + 18432 + kb);
#pragma unroll
                for (int mi = 0; mi < 2; mi++) {
                    // hi*hi
                    mma_bf16(acc[mi][2 * p],     aH[ks][mi], bh0, bh2);
                    mma_bf16(acc[mi][2 * p + 1], aH[ks][mi], bh1, bh3);
                    // lo*hi
                    mma_bf16(acc[mi][2 * p],     aL[ks][mi], bh0, bh2);
                    mma_bf16(acc[mi][2 * p + 1], aL[ks][mi], bh1, bh3);
                    // hi*lo
                    mma_bf16(acc[mi][2 * p],     aH[ks][mi], bl0, bl2);
                    mma_bf16(acc[mi][2 * p + 1], aH[ks][mi], bl1, bl3);
                }
            }
        }

        // ---- epilogue: bias + store (STG.64) ----
        {
            const int qr = lane >> 2;          // 0..7 row within 8
            const int qc = (lane & 3) * 2;     // col pair within 8
#pragma unroll
            for (int ni = 0; ni < 4; ni++) {
                int col = wn * 32 + ni * 8 + qc;
                float b0 = __ldg(bias + col);
                float b1 = __ldg(bias + col + 1);
#pragma unroll
                for (int mi = 0; mi < 2; mi++) {
                    int row = mb + wm * 32 + mi * 16 + qr;
                    size_t idx = (size_t)row * NPRE + (size_t)g * 128 + col;
                    float2 v0 = make_float2(acc[mi][ni][0] + b0, acc[mi][ni][1] + b1);
                    float2 v1 = make_float2(acc[mi][ni][2] + b0, acc[mi][ni][3] + b1);
                    *(float2*)(g_pre + idx) = v0;
                    *(float2*)(g_pre + idx + 8 * NPRE) = v1;
                }
            }
        }
    }
}

// ================= Kernel 2: wavefront recurrence (p2p warp pipeline) ======
__device__ __forceinline__ float sigf(float x) {
    float t;
    asm("tanh.approx.f32 %0, %1;" : "=f"(t) : "f"(0.5f * x));
    return fmaf(0.5f, t, 0.5f);
}
__device__ __forceinline__ float tanhapx(float x) {
    float y;
    asm("tanh.approx.f32 %0, %1;" : "=f"(y) : "f"(x));
    return y;
}

struct UC {
    float uf00, uf01, uf10, uf11;
    float ui0, ui1, uo0, uo1, uc0, uc1;
};

__device__ __forceinline__ void cell_compute(const float q[5], const UC& u,
                                             float hup, float hl,
                                             float sup, float sl,
                                             float& s, float& h)
{
    float pf0 = fmaf(u.uf01, hl, fmaf(u.uf00, hup, q[0]));
    float pf1 = fmaf(u.uf11, hl, fmaf(u.uf10, hup, q[1]));
    float pi  = fmaf(u.ui1,  hl, fmaf(u.ui0,  hup, q[2]));
    float po  = fmaf(u.uo1,  hl, fmaf(u.uo0,  hup, q[3]));
    float pc  = fmaf(u.uc1,  hl, fmaf(u.uc0,  hup, q[4]));
    float f0 = sigf(pf0);
    float f1 = sigf(pf1);
    float ig = sigf(pi);
    float og = sigf(po);
    float cg = sigf(pc);
    s = fmaf(f0, sup, fmaf(f1, sl, ig * cg));
    h = og * tanhapx(s);
}

// block = (b, o-group of 32). 32 warps; warp w owns rows 2w, 2w+1; lane = o.
// Point-to-point producer/consumer sync between adjacent warps:
//   ready[w] = last diagonal step w has completed (st.release / ld.acquire).
//   4-deep slot ring for the row-(2w+1) handoff values.
// Each warp runs ONLY its 65 active steps.
__global__ void __launch_bounds__(1024, 1) mdlstm_rec_kernel(
    const float* __restrict__ uf, const float* __restrict__ ui,
    const float* __restrict__ uo, const float* __restrict__ uc,
    float* __restrict__ out)
{
    __shared__ float sh_s[4][32][32];   // [slot][producer warp][lane]
    __shared__ float sh_h[4][32][32];
    __shared__ int   ready[32];

    const int lane = threadIdx.x & 31;
    const int w    = threadIdx.x >> 5;
    const int b    = blockIdx.x >> 2;
    const int og   = blockIdx.x & 3;
    const int o    = og * 32 + lane;

    if (threadIdx.x < 32) ready[threadIdx.x] = -1;
    __syncthreads();
    const uint32_t raddr = smem_u32(ready);
    const uint32_t r_prev = raddr + 4u * (uint32_t)(w - 1);
    const uint32_t r_next = raddr + 4u * (uint32_t)(w + 1);
    const uint32_t r_self = raddr + 4u * (uint32_t)w;

    UC u;
    u.uf00 = uf[o];        u.uf01 = uf[128 + o];
    u.uf10 = uf[256 + o];  u.uf11 = uf[384 + o];
    u.ui0  = ui[o];        u.ui1  = ui[128 + o];
    u.uo0  = uo[o];        u.uo1  = uo[128 + o];
    u.uc0  = uc[o];        u.uc1  = uc[128 + o];

    const float* preb = g_pre + (size_t)b * NPRE + o;  // + cell*20480
    float* ob = out + b * 128 + o;                     // + cell*4096

    const int r0base = (2 * w) * 64;   // row 2w, col 0 (cell index)
    const int r1base = r0base + 64;    // row 2w+1

    // running pointers
    const float* pf0 = preb + (size_t)r0base * 20480;  // next row0 load (c0=0 first)
    const float* pf1 = preb + (size_t)r1base * 20480;  // next row1 load (c1=0)
    float* ob0 = ob + (size_t)r0base * 4096;
    float* ob1 = ob + (size_t)r1base * 4096;

    float q0[5], q1[5];
    // preload row0 c0=0
#pragma unroll
    for (int z = 0; z < 5; z++) q0[z] = __ldg(pf0 + z * 128);
    pf0 += 20480;

    float s0l = 0.f, h0l = 0.f;
    float s1l = 0.f, h1l = 0.f;

    const int t0 = 2 * w;

#pragma unroll 1
    for (int step = 0; step <= 64; step++) {
        const int t  = t0 + step;
        const int c0 = step;       // row0 column this step (valid if <=63)
        // row1 column = step-1 (valid if >=0)

        // ---- prefetch next pre-activations ----
        float n0[5], n1[5];
        if (step <= 62) {
#pragma unroll
            for (int z = 0; z < 5; z++) n0[z] = __ldg(pf0 + z * 128);
            pf0 += 20480;
        }
        if (step <= 63) {
#pragma unroll
            for (int z = 0; z < 5; z++) n1[z] = __ldg(pf1 + z * 128);
            pf1 += 20480;
        }

        const float s0_prev = s0l, h0_prev = h0l;

        // ---- row 0 (consumes warp w-1's step t-1 publish) ----
        if (c0 <= 63) {
            float sup, hup;
            if (w == 0) {
                sup = 0.f; hup = 0.f;
            } else {
                const int need = t - 1;
                int v;
                do {
                    asm volatile("ld.acquire.cta.shared.b32 %0, [%1];"
                                 : "=r"(v) : "r"(r_prev) : "memory");
                } while (v < need);
                const int ps = need & 3;
                sup = sh_s[ps][w - 1][lane];
                hup = sh_h[ps][w - 1][lane];
            }
            float s, h;
            cell_compute(q0, u, hup, h0l, sup, s0l, s, h);
            *ob0 = s; ob0 += 4096;
            s0l = s; h0l = h;
        }

        // ---- row 1 (publishes for warp w+1) ----
        if (step >= 1) {
            float s, h;
            cell_compute(q1, u, h0_prev, h1l, s0_prev, s1l, s, h);
            *ob1 = s; ob1 += 4096;
            s1l = s; h1l = h;
            if (w < 31) {
                // back-pressure: slot t&3 last held step t-4, read by w+1 at t-3
                if (t >= t0 + 5) {
                    const int need = t - 3;
                    int v;
                    do {
                        asm volatile("ld.acquire.cta.shared.b32 %0, [%1];"
                                     : "=r"(v) : "r"(r_next) : "memory");
                    } while (v < need);
                }
                const int slot = t & 3;
                sh_s[slot][w][lane] = s;
                sh_h[slot][w][lane] = h;
            }
        }

        // ---- publish progress ----
        if (lane == 0) {
            asm volatile("st.release.cta.shared.b32 [%0], %1;"
                         :: "r"(r_self), "r"(t) : "memory");
        }

#pragma unroll
        for (int z = 0; z < 5; z++) { q0[z] = n0[z]; q1[z] = n1[z]; }
    }
}

// ================= launcher =================
extern "C" void kernel_launch(void* const* d_in, const int* in_sizes, int n_in,
                              void* d_out, int out_size) {
    (void)in_sizes; (void)n_in; (void)out_size;
    const float* x     = (const float*)d_in[0];
    const float* wf    = (const float*)d_in[1];
    const float* uf    = (const float*)d_in[2];
    const float* biasf = (const float*)d_in[3];
    const float* wi    = (const float*)d_in[4];
    const float* ui    = (const float*)d_in[5];
    const float* biasi = (const float*)d_in[6];
    const float* wo    = (const float*)d_in[7];
    const float* uo    = (const float*)d_in[8];
    const float* biaso = (const float*)d_in[9];
    const float* wc    = (const float*)d_in[10];
    const float* uc    = (const float*)d_in[11];
    const float* biasc = (const float*)d_in[12];
    float* out = (float*)d_out;

    cudaFuncSetAttribute(gemm_pre_hmma,
                         cudaFuncAttributeMaxDynamicSharedMemorySize, SM_TOTAL);
    gemm_pre_hmma<<<1024, 512, SM_TOTAL>>>(
        x, wf, wi, wo, wc, biasf, biasi, biaso, biasc);
    mdlstm_rec_kernel<<<128, 1024>>>(uf, ui, uo, uc, out);
}